// round 7
// baseline (speedup 1.0000x reference)
#include <cuda_runtime.h>
#include <cstdint>
#include <cstddef>

#define VOCAB   50000
#define EMB     256
#define HID     512
#define NBATCH  256
#define T       512
#define NB      512
#define KTOT    768            // EMB + HID
#define GB_H    32
#define GB_B    4
#define NBLOCKS (GB_H * GB_B)  // 128
#define HS      16             // hid units per block -> 64 gate rows
#define BS      128            // batch rows per block
#define KSPLIT  2
#define KHALF   (KTOT / KSPLIT) // 384
#define KC      16             // K chunk per buffer slot
#define NCHUNK  (KHALF / KC)   // 24
#define THREADS 512
#define NWARP   16
#define RPW     16             // batch rows per warp
#define ROWF    KC             // floats per row per chunk = 16
#define BUFW    (RPW * ROWF)   // 256 floats per (warp,buffer)

// SMEM: weights 49152 floats (192KB) + staging/exchange 8192 floats (32KB) = 229376 B
#define WS_FLOATS   (HS * KTOT * 4)
#define INS_FLOATS  (NWARP * 2 * BUFW)
#define SMEM_BYTES  ((WS_FLOATS + INS_FLOATS) * 4)

__device__ float     g_h[2][NB * HID];
__device__ unsigned  g_cnt;
__device__ unsigned  g_gen;

__device__ __forceinline__ float2 unpack2(unsigned long long v) {
    float lo, hi;
    asm("mov.b64 {%0, %1}, %2;" : "=f"(lo), "=f"(hi) : "l"(v));
    return make_float2(lo, hi);
}
__device__ __forceinline__ float hadd2(unsigned long long v) {
    float2 f = unpack2(v);
    return f.x + f.y;
}
__device__ __forceinline__ void ffma2(unsigned long long& acc,
                                      unsigned long long a, unsigned long long b) {
    asm("fma.rn.f32x2 %0, %1, %2, %0;" : "+l"(acc) : "l"(a), "l"(b));
}
__device__ __forceinline__ void cp16_ca(void* dst, const void* src) {
    unsigned d = (unsigned)__cvta_generic_to_shared(dst);
    asm volatile("cp.async.ca.shared.global [%0], [%1], 16;" :: "r"(d), "l"(src));
}
__device__ __forceinline__ void cp16_cg(void* dst, const void* src) {
    unsigned d = (unsigned)__cvta_generic_to_shared(dst);
    asm volatile("cp.async.cg.shared.global [%0], [%1], 16;" :: "r"(d), "l"(src));
}
__device__ __forceinline__ float sigf(float x) {
    return __fdividef(1.0f, 1.0f + __expf(-x));
}
__device__ __forceinline__ float tanhx(float x) {
    return __fmaf_rn(2.0f, sigf(2.0f * x), -1.0f);
}

__device__ __forceinline__ void grid_sync() {
    __syncthreads();
    if (threadIdx.x == 0) {
        volatile unsigned* genp = &g_gen;
        unsigned g = *genp;
        __threadfence();
        if (atomicAdd(&g_cnt, 1u) == NBLOCKS - 1) {
            g_cnt = 0;
            __threadfence();
            *genp = g + 1;
        } else {
            while (*genp == g) { __nanosleep(40); }
        }
    }
    __syncthreads();
}

__global__ void __launch_bounds__(THREADS, 1)
lstm_twin_kernel(const int* __restrict__ in1, const int* __restrict__ in2,
                 const float* __restrict__ emb, const float* __restrict__ Wih,
                 const float* __restrict__ Whh, const float* __restrict__ bih,
                 const float* __restrict__ bhh, const float* __restrict__ Wfc,
                 const float* __restrict__ bfc, float* __restrict__ out)
{
    extern __shared__ float smem[];
    float* Ws  = smem;
    float* ins = smem + WS_FLOATS;

    const int tid = threadIdx.x;
    const int bid = blockIdx.x;
    const int hg  = bid & (GB_H - 1);
    const int bg  = bid >> 5;
    const int w   = tid >> 5;            // warp 0..15
    const int lid = tid & 31;
    const int ks  = tid >> 8;            // k-split half 0/1
    const int wr  = w & 7;               // row-block within half
    const int tbw = (tid >> 4) & 1;      // row parity within warp
    const int tj  = tid & 15;            // hid unit within tile
    const int jglob = hg * HS + tj;
    const int nbase = bg * BS;
    const int nbw   = nbase + wr * RPW;  // warp's first batch row
    const int kbase = ks * KHALF;
    const int warpbase = w * 2 * BUFW;

    // ---- weight tile -> SMEM, k-pair layout, NO swizzle ----
    // cell ci = (kp*2 + qq)*16 + tj  (16B each):
    //   { W[2qq+0][2kp], W[2qq+0][2kp+1], W[2qq+1][2kp], W[2qq+1][2kp+1] }
    for (int f = tid; f < WS_FLOATS; f += THREADS) {
        const int ci  = f >> 2;
        const int e   = f & 3;
        const int tjr = ci & 15;
        const int qq  = (ci >> 4) & 1;
        const int kp  = ci >> 5;
        const int q   = 2 * qq + (e >> 1);
        const int k   = 2 * kp + (e & 1);
        const int G   = q * HID + hg * HS + tjr;
        Ws[f] = (k < EMB) ? Wih[G * EMB + k] : Whh[G * HID + (k - EMB)];
    }

    // bias per gate (scalars, used by ks==0 combine)
    const float4 biasv = make_float4(
        bih[0 * HID + jglob] + bhh[0 * HID + jglob],
        bih[1 * HID + jglob] + bhh[1 * HID + jglob],
        bih[2 * HID + jglob] + bhh[2 * HID + jglob],
        bih[3 * HID + jglob] + bhh[3 * HID + jglob]);

    // zero h buffer 0
    {
        float* hz = &g_h[0][0];
        int base = (bid * THREADS + tid) * 4;
#pragma unroll
        for (int i = 0; i < 4; i++) hz[base + i] = 0.0f;
    }
    grid_sync();

    // ---- warp-private staging: 64 cells (16B) per chunk, 2 per lane ----
    const int sc  = lid & 3;              // cell column 0..3
    const int scf = sc * 4;               // float offset within row-chunk
    const int sr0 = lid >> 2;             // rows 0..7
    const int sr1 = sr0 + 8;              // rows 8..15
    const int d0  = sr0 * ROWF + ((sc ^ (sr0 & 3)) << 2);
    const int d1  = sr1 * ROWF + ((sc ^ (sr1 & 3)) << 2);
    const int gr0 = nbw + sr0;
    const int gr1 = nbw + sr1;

    const int* tokarr = (bg < 2) ? in1 : in2;
    const int  rowb   = (nbase & (NBATCH - 1)) + wr * RPW;
    const int* tp0 = tokarr + (size_t)(rowb + sr0) * T;
    const int* tp1 = tokarr + (size_t)(rowb + sr1) * T;

    int cur0 = __ldg(tp0);
    int cur1 = __ldg(tp1);

    float c[8];
#pragma unroll
    for (int b = 0; b < 8; b++) c[b] = 0.0f;

#pragma unroll 1
    for (int t = 0; t < T; t++) {
        const float* hread  = &g_h[t & 1][0];
        float*       hwrite = &g_h[(t + 1) & 1][0];

        const float* e0 = emb + (size_t)cur0 * EMB + scf;
        const float* e1 = emb + (size_t)cur1 * EMB + scf;
        const float* h0 = hread + (size_t)gr0 * HID + scf - EMB;
        const float* h1 = hread + (size_t)gr1 * HID + scf - EMB;

        // stage chunks 0 and 1
#pragma unroll
        for (int cc = 0; cc < 2; cc++) {
            const int kabs = kbase + cc * KC;
            float* dst = ins + warpbase + (cc & 1) * BUFW;
            if (kabs < EMB) {
                cp16_ca(dst + d0, e0 + kabs);
                cp16_ca(dst + d1, e1 + kabs);
            } else {
                cp16_cg(dst + d0, h0 + kabs);
                cp16_cg(dst + d1, h1 + kabs);
            }
            asm volatile("cp.async.commit_group;");
        }

        const int tn = (t + 1 < T) ? t + 1 : t;
        int nxt0 = __ldg(tp0 + tn);
        int nxt1 = __ldg(tp1 + tn);

        // acc[b][q]: f32x2, lanes = (even-k sum, odd-k sum) for gate q
        unsigned long long acc[8][4];
#pragma unroll
        for (int b = 0; b < 8; b++)
#pragma unroll
            for (int q = 0; q < 4; q++) acc[b][q] = 0ull;

#pragma unroll 1
        for (int cch = 0; cch < NCHUNK; cch++) {
            if (cch == NCHUNK - 1) {
                asm volatile("cp.async.wait_group 0;");
            } else {
                asm volatile("cp.async.wait_group 1;");
            }

            const float* xb = ins + warpbase + (cch & 1) * BUFW;
            const int kpb = (kbase + cch * KC) >> 1;   // first k-pair of chunk
#pragma unroll
            for (int kk = 0; kk < KC / 4; kk++) {
                const int kp = kpb + kk * 2;
                const ulonglong2* Wc = (const ulonglong2*)Ws;
                ulonglong2 wA0 = Wc[(kp * 2 + 0) * 16 + tj];   // gates01, kpair kp
                ulonglong2 wB0 = Wc[(kp * 2 + 1) * 16 + tj];   // gates23, kpair kp
                ulonglong2 wA1 = Wc[(kp * 2 + 2) * 16 + tj];   // gates01, kpair kp+1
                ulonglong2 wB1 = Wc[(kp * 2 + 3) * 16 + tj];   // gates23, kpair kp+1
#pragma unroll
                for (int b = 0; b < 8; b++) {
                    const int r = 2 * b + tbw;
                    ulonglong2 x = *(const ulonglong2*)(xb + r * ROWF + ((kk ^ (r & 3)) << 2));
                    ffma2(acc[b][0], x.x, wA0.x);
                    ffma2(acc[b][1], x.x, wA0.y);
                    ffma2(acc[b][2], x.x, wB0.x);
                    ffma2(acc[b][3], x.x, wB0.y);
                    ffma2(acc[b][0], x.y, wA1.x);
                    ffma2(acc[b][1], x.y, wA1.y);
                    ffma2(acc[b][2], x.y, wB1.x);
                    ffma2(acc[b][3], x.y, wB1.y);
                }
            }

            if (cch + 2 < NCHUNK) {
                const int kabs = kbase + (cch + 2) * KC;
                float* dst = ins + warpbase + (cch & 1) * BUFW;
                if (kabs < EMB) {
                    cp16_ca(dst + d0, e0 + kabs);
                    cp16_ca(dst + d1, e1 + kabs);
                } else {
                    cp16_cg(dst + d0, h0 + kabs);
                    cp16_cg(dst + d1, h1 + kabs);
                }
                asm volatile("cp.async.commit_group;");
            }
        }

        // ---- cross-half reduction (scalar gates) + pointwise ----
        __syncthreads();
        if (ks) {
            const int col = tid & 255;
#pragma unroll
            for (int b = 0; b < 8; b++) {
                *(float4*)(ins + b * 1024 + col * 4) = make_float4(
                    hadd2(acc[b][0]), hadd2(acc[b][1]),
                    hadd2(acc[b][2]), hadd2(acc[b][3]));
            }
        }
        __syncthreads();
        if (!ks) {
#pragma unroll
            for (int b = 0; b < 8; b++) {
                float4 p = *(const float4*)(ins + b * 1024 + tid * 4);
                float gi = hadd2(acc[b][0]) + p.x + biasv.x;
                float gf = hadd2(acc[b][1]) + p.y + biasv.y;
                float gc = hadd2(acc[b][2]) + p.z + biasv.z;
                float go = hadd2(acc[b][3]) + p.w + biasv.w;
                float ig = sigf(gi);
                float fg = sigf(gf);
                float gg = tanhx(gc);
                float og = sigf(go);
                c[b] = fg * c[b] + ig * gg;
                float hv = og * tanhx(c[b]);
                hwrite[(size_t)(nbw + 2 * b + tbw) * HID + jglob] = hv;
            }
        }

        cur0 = nxt0;
        cur1 = nxt1;
        grid_sync();
    }

    // epilogue: h = h1*h2 -> FC(2) -> softmax
    if (bid == 0 && tid < NBATCH) {
        const int n = tid;
        const float* h1 = &g_h[0][(size_t)n * HID];
        const float* h2 = &g_h[0][(size_t)(n + NBATCH) * HID];
        float l0 = bfc[0], l1 = bfc[1];
#pragma unroll 4
        for (int j = 0; j < HID; j++) {
            float hp = __ldcg(&h1[j]) * __ldcg(&h2[j]);
            l0 = __fmaf_rn(hp, Wfc[j], l0);
            l1 = __fmaf_rn(hp, Wfc[HID + j], l1);
        }
        float m  = fmaxf(l0, l1);
        float e0 = __expf(l0 - m);
        float e1 = __expf(l1 - m);
        float s  = __fdividef(1.0f, e0 + e1);
        out[n * 2 + 0] = e0 * s;
        out[n * 2 + 1] = e1 * s;
    }
}

extern "C" void kernel_launch(void* const* d_in, const int* in_sizes, int n_in,
                              void* d_out, int out_size)
{
    (void)in_sizes; (void)n_in; (void)out_size;
    const int*   in1 = (const int*)d_in[0];
    const int*   in2 = (const int*)d_in[1];
    const float* emb = (const float*)d_in[2];
    const float* Wih = (const float*)d_in[3];
    const float* Whh = (const float*)d_in[4];
    const float* bih = (const float*)d_in[5];
    const float* bhh = (const float*)d_in[6];
    const float* Wfc = (const float*)d_in[7];
    const float* bfc = (const float*)d_in[8];
    float* out = (float*)d_out;

    cudaFuncSetAttribute(lstm_twin_kernel,
                         cudaFuncAttributeMaxDynamicSharedMemorySize, SMEM_BYTES);
    lstm_twin_kernel<<<NBLOCKS, THREADS, SMEM_BYTES>>>(
        in1, in2, emb, Wih, Whh, bih, bhh, Wfc, bfc, out);
}

// round 8
// speedup vs baseline: 1.0001x; 1.0001x over previous
#include <cuda_runtime.h>
#include <cstdint>
#include <cstddef>

#define VOCAB   50000
#define EMB     256
#define HID     512
#define NBATCH  256
#define T       512
#define NB      512
#define KTOT    768            // EMB + HID
#define GB_H    32
#define GB_B    4
#define NBLOCKS (GB_H * GB_B)  // 128
#define HS      16             // hid units per block -> 64 gate rows
#define BS      128            // batch rows per block
#define KSPLIT  2
#define KHALF   (KTOT / KSPLIT) // 384
#define KC      16             // K chunk per buffer slot
#define NCHUNK  (KHALF / KC)   // 24
#define THREADS 512
#define NWARP   16
#define RPW     16             // batch rows per warp
#define ROWF    KC             // floats per row per chunk = 16
#define BUFW    (RPW * ROWF)   // 256 floats per (warp,buffer)

// SMEM: weights 49152 floats (192KB) + staging/exchange 8192 floats (32KB) = 229376 B
#define WS_FLOATS   (HS * KTOT * 4)
#define INS_FLOATS  (NWARP * 2 * BUFW)
#define SMEM_BYTES  ((WS_FLOATS + INS_FLOATS) * 4)

__device__ float     g_h[2][NB * HID];
__device__ unsigned  g_cnt;
__device__ unsigned  g_gen;

__device__ __forceinline__ float2 unpack2(unsigned long long v) {
    float lo, hi;
    asm("mov.b64 {%0, %1}, %2;" : "=f"(lo), "=f"(hi) : "l"(v));
    return make_float2(lo, hi);
}
__device__ __forceinline__ float hadd2(unsigned long long v) {
    float2 f = unpack2(v);
    return f.x + f.y;
}
__device__ __forceinline__ void ffma2(unsigned long long& acc,
                                      unsigned long long a, unsigned long long b) {
    asm("fma.rn.f32x2 %0, %1, %2, %0;" : "+l"(acc) : "l"(a), "l"(b));
}
__device__ __forceinline__ void cp16_ca(void* dst, const void* src) {
    unsigned d = (unsigned)__cvta_generic_to_shared(dst);
    asm volatile("cp.async.ca.shared.global [%0], [%1], 16;" :: "r"(d), "l"(src));
}
__device__ __forceinline__ void cp16_cg(void* dst, const void* src) {
    unsigned d = (unsigned)__cvta_generic_to_shared(dst);
    asm volatile("cp.async.cg.shared.global [%0], [%1], 16;" :: "r"(d), "l"(src));
}
__device__ __forceinline__ float sigf(float x) {
    return __fdividef(1.0f, 1.0f + __expf(-x));
}
__device__ __forceinline__ float tanhx(float x) {
    return __fmaf_rn(2.0f, sigf(2.0f * x), -1.0f);
}

__device__ __forceinline__ void grid_sync() {
    __syncthreads();
    if (threadIdx.x == 0) {
        volatile unsigned* genp = &g_gen;
        unsigned g = *genp;
        __threadfence();
        if (atomicAdd(&g_cnt, 1u) == NBLOCKS - 1) {
            g_cnt = 0;
            __threadfence();
            *genp = g + 1;
        } else {
            while (*genp == g) { __nanosleep(40); }
        }
    }
    __syncthreads();
}

__global__ void __launch_bounds__(THREADS, 1)
lstm_twin_kernel(const int* __restrict__ in1, const int* __restrict__ in2,
                 const float* __restrict__ emb, const float* __restrict__ Wih,
                 const float* __restrict__ Whh, const float* __restrict__ bih,
                 const float* __restrict__ bhh, const float* __restrict__ Wfc,
                 const float* __restrict__ bfc, float* __restrict__ out)
{
    extern __shared__ float smem[];
    float* Ws  = smem;
    float* ins = smem + WS_FLOATS;

    const int tid = threadIdx.x;
    const int bid = blockIdx.x;
    const int hg  = bid & (GB_H - 1);
    const int bg  = bid >> 5;
    const int w   = tid >> 5;            // warp 0..15
    const int lid = tid & 31;
    const int ks  = tid >> 8;            // k-split half 0/1
    const int wr  = w & 7;               // row-block within half
    const int tbw = (tid >> 4) & 1;      // row parity within warp
    const int tj  = tid & 15;            // hid unit within tile
    const int jglob = hg * HS + tj;
    const int nbase = bg * BS;
    const int nbw   = nbase + wr * RPW;  // warp's first batch row
    const int kbase = ks * KHALF;
    const int warpbase = w * 2 * BUFW;

    // ---- weight tile -> SMEM, k-pair layout, NO swizzle ----
    // cell ci = (kp*2 + qq)*16 + tj  (16B each):
    //   { W[2qq+0][2kp], W[2qq+0][2kp+1], W[2qq+1][2kp], W[2qq+1][2kp+1] }
    for (int f = tid; f < WS_FLOATS; f += THREADS) {
        const int ci  = f >> 2;
        const int e   = f & 3;
        const int tjr = ci & 15;
        const int qq  = (ci >> 4) & 1;
        const int kp  = ci >> 5;
        const int q   = 2 * qq + (e >> 1);
        const int k   = 2 * kp + (e & 1);
        const int G   = q * HID + hg * HS + tjr;
        Ws[f] = (k < EMB) ? Wih[G * EMB + k] : Whh[G * HID + (k - EMB)];
    }

    // bias per gate (scalars, used by ks==0 combine)
    const float4 biasv = make_float4(
        bih[0 * HID + jglob] + bhh[0 * HID + jglob],
        bih[1 * HID + jglob] + bhh[1 * HID + jglob],
        bih[2 * HID + jglob] + bhh[2 * HID + jglob],
        bih[3 * HID + jglob] + bhh[3 * HID + jglob]);

    // zero h buffer 0
    {
        float* hz = &g_h[0][0];
        int base = (bid * THREADS + tid) * 4;
#pragma unroll
        for (int i = 0; i < 4; i++) hz[base + i] = 0.0f;
    }
    grid_sync();

    // ---- warp-private staging: 64 cells (16B) per chunk, 2 per lane ----
    const int sc  = lid & 3;              // cell column 0..3
    const int scf = sc * 4;               // float offset within row-chunk
    const int sr0 = lid >> 2;             // rows 0..7
    const int sr1 = sr0 + 8;              // rows 8..15
    const int d0  = sr0 * ROWF + ((sc ^ (sr0 & 3)) << 2);
    const int d1  = sr1 * ROWF + ((sc ^ (sr1 & 3)) << 2);
    const int gr0 = nbw + sr0;
    const int gr1 = nbw + sr1;

    const int* tokarr = (bg < 2) ? in1 : in2;
    const int  rowb   = (nbase & (NBATCH - 1)) + wr * RPW;
    const int* tp0 = tokarr + (size_t)(rowb + sr0) * T;
    const int* tp1 = tokarr + (size_t)(rowb + sr1) * T;

    int cur0 = __ldg(tp0);
    int cur1 = __ldg(tp1);

    float c[8];
#pragma unroll
    for (int b = 0; b < 8; b++) c[b] = 0.0f;

#pragma unroll 1
    for (int t = 0; t < T; t++) {
        const float* hread  = &g_h[t & 1][0];
        float*       hwrite = &g_h[(t + 1) & 1][0];

        const float* e0 = emb + (size_t)cur0 * EMB + scf;
        const float* e1 = emb + (size_t)cur1 * EMB + scf;
        const float* h0 = hread + (size_t)gr0 * HID + scf - EMB;
        const float* h1 = hread + (size_t)gr1 * HID + scf - EMB;

        // stage chunks 0 and 1
#pragma unroll
        for (int cc = 0; cc < 2; cc++) {
            const int kabs = kbase + cc * KC;
            float* dst = ins + warpbase + (cc & 1) * BUFW;
            if (kabs < EMB) {
                cp16_ca(dst + d0, e0 + kabs);
                cp16_ca(dst + d1, e1 + kabs);
            } else {
                cp16_cg(dst + d0, h0 + kabs);
                cp16_cg(dst + d1, h1 + kabs);
            }
            asm volatile("cp.async.commit_group;");
        }

        const int tn = (t + 1 < T) ? t + 1 : t;
        int nxt0 = __ldg(tp0 + tn);
        int nxt1 = __ldg(tp1 + tn);

        // acc[b][q]: f32x2, lanes = (even-k sum, odd-k sum) for gate q
        unsigned long long acc[8][4];
#pragma unroll
        for (int b = 0; b < 8; b++)
#pragma unroll
            for (int q = 0; q < 4; q++) acc[b][q] = 0ull;

#pragma unroll 1
        for (int cch = 0; cch < NCHUNK; cch++) {
            if (cch == NCHUNK - 1) {
                asm volatile("cp.async.wait_group 0;");
            } else {
                asm volatile("cp.async.wait_group 1;");
            }

            const float* xb = ins + warpbase + (cch & 1) * BUFW;
            const int kpb = (kbase + cch * KC) >> 1;   // first k-pair of chunk
#pragma unroll
            for (int kk = 0; kk < KC / 4; kk++) {
                const int kp = kpb + kk * 2;
                const ulonglong2* Wc = (const ulonglong2*)Ws;
                ulonglong2 wA0 = Wc[(kp * 2 + 0) * 16 + tj];   // gates01, kpair kp
                ulonglong2 wB0 = Wc[(kp * 2 + 1) * 16 + tj];   // gates23, kpair kp
                ulonglong2 wA1 = Wc[(kp * 2 + 2) * 16 + tj];   // gates01, kpair kp+1
                ulonglong2 wB1 = Wc[(kp * 2 + 3) * 16 + tj];   // gates23, kpair kp+1
#pragma unroll
                for (int b = 0; b < 8; b++) {
                    const int r = 2 * b + tbw;
                    ulonglong2 x = *(const ulonglong2*)(xb + r * ROWF + ((kk ^ (r & 3)) << 2));
                    ffma2(acc[b][0], x.x, wA0.x);
                    ffma2(acc[b][1], x.x, wA0.y);
                    ffma2(acc[b][2], x.x, wB0.x);
                    ffma2(acc[b][3], x.x, wB0.y);
                    ffma2(acc[b][0], x.y, wA1.x);
                    ffma2(acc[b][1], x.y, wA1.y);
                    ffma2(acc[b][2], x.y, wB1.x);
                    ffma2(acc[b][3], x.y, wB1.y);
                }
            }

            if (cch + 2 < NCHUNK) {
                const int kabs = kbase + (cch + 2) * KC;
                float* dst = ins + warpbase + (cch & 1) * BUFW;
                if (kabs < EMB) {
                    cp16_ca(dst + d0, e0 + kabs);
                    cp16_ca(dst + d1, e1 + kabs);
                } else {
                    cp16_cg(dst + d0, h0 + kabs);
                    cp16_cg(dst + d1, h1 + kabs);
                }
                asm volatile("cp.async.commit_group;");
            }
        }

        // ---- cross-half reduction (scalar gates) + pointwise ----
        __syncthreads();
        if (ks) {
            const int col = tid & 255;
#pragma unroll
            for (int b = 0; b < 8; b++) {
                *(float4*)(ins + b * 1024 + col * 4) = make_float4(
                    hadd2(acc[b][0]), hadd2(acc[b][1]),
                    hadd2(acc[b][2]), hadd2(acc[b][3]));
            }
        }
        __syncthreads();
        if (!ks) {
#pragma unroll
            for (int b = 0; b < 8; b++) {
                float4 p = *(const float4*)(ins + b * 1024 + tid * 4);
                float gi = hadd2(acc[b][0]) + p.x + biasv.x;
                float gf = hadd2(acc[b][1]) + p.y + biasv.y;
                float gc = hadd2(acc[b][2]) + p.z + biasv.z;
                float go = hadd2(acc[b][3]) + p.w + biasv.w;
                float ig = sigf(gi);
                float fg = sigf(gf);
                float gg = tanhx(gc);
                float og = sigf(go);
                c[b] = fg * c[b] + ig * gg;
                float hv = og * tanhx(c[b]);
                hwrite[(size_t)(nbw + 2 * b + tbw) * HID + jglob] = hv;
            }
        }

        cur0 = nxt0;
        cur1 = nxt1;
        grid_sync();
    }

    // epilogue: h = h1*h2 -> FC(2) -> softmax
    if (bid == 0 && tid < NBATCH) {
        const int n = tid;
        const float* h1 = &g_h[0][(size_t)n * HID];
        const float* h2 = &g_h[0][(size_t)(n + NBATCH) * HID];
        float l0 = bfc[0], l1 = bfc[1];
#pragma unroll 4
        for (int j = 0; j < HID; j++) {
            float hp = __ldcg(&h1[j]) * __ldcg(&h2[j]);
            l0 = __fmaf_rn(hp, Wfc[j], l0);
            l1 = __fmaf_rn(hp, Wfc[HID + j], l1);
        }
        float m  = fmaxf(l0, l1);
        float e0 = __expf(l0 - m);
        float e1 = __expf(l1 - m);
        float s  = __fdividef(1.0f, e0 + e1);
        out[n * 2 + 0] = e0 * s;
        out[n * 2 + 1] = e1 * s;
    }
}

extern "C" void kernel_launch(void* const* d_in, const int* in_sizes, int n_in,
                              void* d_out, int out_size)
{
    (void)in_sizes; (void)n_in; (void)out_size;
    const int*   in1 = (const int*)d_in[0];
    const int*   in2 = (const int*)d_in[1];
    const float* emb = (const float*)d_in[2];
    const float* Wih = (const float*)d_in[3];
    const float* Whh = (const float*)d_in[4];
    const float* bih = (const float*)d_in[5];
    const float* bhh = (const float*)d_in[6];
    const float* Wfc = (const float*)d_in[7];
    const float* bfc = (const float*)d_in[8];
    float* out = (float*)d_out;

    cudaFuncSetAttribute(lstm_twin_kernel,
                         cudaFuncAttributeMaxDynamicSharedMemorySize, SMEM_BYTES);
    lstm_twin_kernel<<<NBLOCKS, THREADS, SMEM_BYTES>>>(
        in1, in2, emb, Wih, Whh, bih, bhh, Wfc, bfc, out);
}